// round 1
// baseline (speedup 1.0000x reference)
#include <cuda_runtime.h>

#define D      512
#define WGRP   1536
#define MGRP   64
#define TB     30000
#define KTOP   5
#define SEGS   12
#define SEGLEN 2500
#define BM     128
#define BN     128
#define BK     16
#define NKB    (D / BK)                    // 32
#define NCHUNK ((SEGLEN + BN - 1) / BN)    // 20
#define PADL   132

// scratch (no allocations allowed)
__device__ float g_a[WGRP * D];
__device__ float g_invt[TB];
__device__ float g_pv[SEGS * WGRP * KTOP];
__device__ int   g_pi[SEGS * WGRP * KTOP];
__device__ float g_topk[WGRP * D];

typedef unsigned long long ull;

__device__ __forceinline__ ull pk2(float lo, float hi) {
    ull r; asm("mov.b64 %0, {%1, %2};" : "=l"(r) : "f"(lo), "f"(hi)); return r;
}
__device__ __forceinline__ void unpk2(ull v, float& lo, float& hi) {
    asm("mov.b64 {%0, %1}, %2;" : "=f"(lo), "=f"(hi) : "l"(v));
}
__device__ __forceinline__ void fma2(ull& d, ull a, ull b) {
    asm("fma.rn.f32x2 %0, %1, %2, %0;" : "+l"(d) : "l"(a), "l"(b));
}

// sorted-descending top-5 insert; strict > keeps earlier (lower-index) on ties,
// matching jax.lax.top_k tie-breaking when candidates arrive in ascending index order.
__device__ __forceinline__ void ins5(float (&tv)[5], int (&ti)[5], float v, int c) {
    if (v > tv[4]) {
#pragma unroll
        for (int s = 0; s < 5; s++) {
            bool g = v > tv[s];
            float fn = g ? v : tv[s];
            float fo = g ? tv[s] : v;
            int   in_ = g ? c : ti[s];
            int   io  = g ? ti[s] : c;
            tv[s] = fn; v = fo; ti[s] = in_; c = io;
        }
    }
}

// ---------------- Kernel A: group mean (64 rows) + L2-normalize ----------------
__global__ __launch_bounds__(128)
void k_avg_norm(const float* __restrict__ x) {
    int g = blockIdx.x, t = threadIdx.x;
    const float* p = x + (size_t)g * (MGRP * D) + t * 4;
    float4 s0 = make_float4(0.f, 0.f, 0.f, 0.f), s1 = s0;
#pragma unroll 4
    for (int r = 0; r < MGRP; r += 2) {
        float4 a  = *(const float4*)(p + (size_t)r * D);
        float4 b2 = *(const float4*)(p + (size_t)(r + 1) * D);
        s0.x += a.x;  s0.y += a.y;  s0.z += a.z;  s0.w += a.w;
        s1.x += b2.x; s1.y += b2.y; s1.z += b2.z; s1.w += b2.w;
    }
    float4 m;
    m.x = (s0.x + s1.x) * (1.0f / 64.0f);
    m.y = (s0.y + s1.y) * (1.0f / 64.0f);
    m.z = (s0.z + s1.z) * (1.0f / 64.0f);
    m.w = (s0.w + s1.w) * (1.0f / 64.0f);
    float ss = m.x * m.x + m.y * m.y + m.z * m.z + m.w * m.w;
    __shared__ float red[128];
    red[t] = ss;
    __syncthreads();
    for (int o = 64; o > 0; o >>= 1) {
        if (t < o) red[t] += red[t + o];
        __syncthreads();
    }
    float inv = 1.0f / fmaxf(sqrtf(red[0]), 1e-8f);
    m.x *= inv; m.y *= inv; m.z *= inv; m.w *= inv;
    *(float4*)(g_a + (size_t)g * D + t * 4) = m;
}

// ---------------- Kernel B: 1 / max(||t_row||, eps) ----------------
__global__ __launch_bounds__(256)
void k_tinv(const float* __restrict__ tb) {
    int row  = blockIdx.x * 8 + (threadIdx.x >> 5);
    int lane = threadIdx.x & 31;
    const float4* p = (const float4*)(tb + (size_t)row * D);
    float ss = 0.f;
#pragma unroll
    for (int i = 0; i < 4; i++) {
        float4 v = p[lane + 32 * i];
        ss += v.x * v.x + v.y * v.y + v.z * v.z + v.w * v.w;
    }
#pragma unroll
    for (int o = 16; o > 0; o >>= 1) ss += __shfl_xor_sync(0xffffffffu, ss, o);
    if (lane == 0) g_invt[row] = 1.0f / fmaxf(sqrtf(ss), 1e-8f);
}

// ---------------- Kernel C: fp32x2 SGEMM (a_norm @ t.T) fused with top-5 ----------------
__global__ __launch_bounds__(256, 1)
void k_cos_topk(const float* __restrict__ tb) {
    __shared__ float As[BK][PADL];
    __shared__ float Bs[BK][PADL];
    const int tid = threadIdx.x;
    const int tx = tid & 15, ty = tid >> 4;
    const int rowblk = blockIdx.x, seg = blockIdx.y;
    const int segbase = seg * SEGLEN;
    const int cend = segbase + SEGLEN;
    const float* Ab = g_a + (size_t)rowblk * BM * D;

    float tv[8][5]; int ti[8][5];
#pragma unroll
    for (int i = 0; i < 8; i++)
#pragma unroll
        for (int s = 0; s < 5; s++) { tv[i][s] = -1e30f; ti[i][s] = 0; }

    const int sa0 = tid, sa1 = tid + 256;
    const int ar0 = sa0 >> 2, ak0 = sa0 & 3;
    const int ar1 = sa1 >> 2, ak1 = sa1 & 3;

    for (int chunk = 0; chunk < NCHUNK; chunk++) {
        const int c0 = segbase + chunk * BN;
        ull acc[8][4];
#pragma unroll
        for (int i = 0; i < 8; i++)
#pragma unroll
            for (int j = 0; j < 4; j++) acc[i][j] = 0ull;

        const int bc0 = c0 + ar0, bc1 = c0 + ar1;
        const bool v0 = bc0 < TB, v1 = bc1 < TB;
        const float* Ap0 = Ab + (size_t)ar0 * D + ak0 * 4;
        const float* Ap1 = Ab + (size_t)ar1 * D + ak1 * 4;
        const float* Bp0 = tb + (size_t)bc0 * D + ak0 * 4;
        const float* Bp1 = tb + (size_t)bc1 * D + ak1 * 4;

        float4 ra0 = *(const float4*)Ap0;
        float4 ra1 = *(const float4*)Ap1;
        float4 rb0 = v0 ? *(const float4*)Bp0 : make_float4(0.f, 0.f, 0.f, 0.f);
        float4 rb1 = v1 ? *(const float4*)Bp1 : make_float4(0.f, 0.f, 0.f, 0.f);

        for (int kb = 0; kb < NKB; kb++) {
            As[ak0 * 4 + 0][ar0] = ra0.x; As[ak0 * 4 + 1][ar0] = ra0.y;
            As[ak0 * 4 + 2][ar0] = ra0.z; As[ak0 * 4 + 3][ar0] = ra0.w;
            As[ak1 * 4 + 0][ar1] = ra1.x; As[ak1 * 4 + 1][ar1] = ra1.y;
            As[ak1 * 4 + 2][ar1] = ra1.z; As[ak1 * 4 + 3][ar1] = ra1.w;
            Bs[ak0 * 4 + 0][ar0] = rb0.x; Bs[ak0 * 4 + 1][ar0] = rb0.y;
            Bs[ak0 * 4 + 2][ar0] = rb0.z; Bs[ak0 * 4 + 3][ar0] = rb0.w;
            Bs[ak1 * 4 + 0][ar1] = rb1.x; Bs[ak1 * 4 + 1][ar1] = rb1.y;
            Bs[ak1 * 4 + 2][ar1] = rb1.z; Bs[ak1 * 4 + 3][ar1] = rb1.w;
            __syncthreads();
            if (kb + 1 < NKB) {
                int off = (kb + 1) * BK;
                ra0 = *(const float4*)(Ap0 + off);
                ra1 = *(const float4*)(Ap1 + off);
                rb0 = v0 ? *(const float4*)(Bp0 + off) : make_float4(0.f, 0.f, 0.f, 0.f);
                rb1 = v1 ? *(const float4*)(Bp1 + off) : make_float4(0.f, 0.f, 0.f, 0.f);
            }
#pragma unroll
            for (int k = 0; k < BK; k++) {
                float4 a0 = *(const float4*)&As[k][ty * 8];
                float4 a1 = *(const float4*)&As[k][ty * 8 + 4];
                ulonglong2 b0 = *(const ulonglong2*)&Bs[k][tx * 8];
                ulonglong2 b1 = *(const ulonglong2*)&Bs[k][tx * 8 + 4];
                ull bq0 = b0.x, bq1 = b0.y, bq2 = b1.x, bq3 = b1.y;
                float af[8] = {a0.x, a0.y, a0.z, a0.w, a1.x, a1.y, a1.z, a1.w};
#pragma unroll
                for (int i = 0; i < 8; i++) {
                    ull ap = pk2(af[i], af[i]);
                    fma2(acc[i][0], ap, bq0);
                    fma2(acc[i][1], ap, bq1);
                    fma2(acc[i][2], ap, bq2);
                    fma2(acc[i][3], ap, bq3);
                }
            }
            __syncthreads();
        }

        // fused top-5 update (ascending column order within this thread's slice)
        const int cb = c0 + tx * 8;
        float inv[8];
#pragma unroll
        for (int j = 0; j < 8; j++) inv[j] = (cb + j < TB) ? g_invt[cb + j] : 0.0f;
#pragma unroll
        for (int i = 0; i < 8; i++) {
#pragma unroll
            for (int jp = 0; jp < 4; jp++) {
                float x, y; unpk2(acc[i][jp], x, y);
                int c = cb + jp * 2;
                x *= inv[jp * 2]; y *= inv[jp * 2 + 1];
                if (c < cend)     ins5(tv[i], ti[i], x, c);
                if (c + 1 < cend) ins5(tv[i], ti[i], y, c + 1);
            }
        }
    }

    // merge the 16 column-slices of each row via half-warp butterfly shuffles
#pragma unroll
    for (int r = 1; r <= 8; r <<= 1) {
#pragma unroll
        for (int i = 0; i < 8; i++) {
            float ov[5]; int oi[5];
#pragma unroll
            for (int s = 0; s < 5; s++) {
                ov[s] = __shfl_xor_sync(0xffffffffu, tv[i][s], r);
                oi[s] = __shfl_xor_sync(0xffffffffu, ti[i][s], r);
            }
#pragma unroll
            for (int s = 0; s < 5; s++) ins5(tv[i], ti[i], ov[s], oi[s]);
        }
    }
    if (tx == 0) {
#pragma unroll
        for (int i = 0; i < 8; i++) {
            int rowg = rowblk * BM + ty * 8 + i;
            size_t base = ((size_t)seg * WGRP + rowg) * KTOP;
#pragma unroll
            for (int s = 0; s < 5; s++) { g_pv[base + s] = tv[i][s]; g_pi[base + s] = ti[i][s]; }
        }
    }
}

// ---------------- Kernel D: merge segment partials, gather + mean ----------------
__global__ __launch_bounds__(256)
void k_merge_avg(const float* __restrict__ tb) {
    int row = blockIdx.x;
    __shared__ int sidx[KTOP];
    if (threadIdx.x == 0) {
        float tv[5] = {-1e30f, -1e30f, -1e30f, -1e30f, -1e30f};
        int ti[5] = {0, 0, 0, 0, 0};
        for (int s = 0; s < SEGS; s++) {  // ascending segment = ascending column order
            size_t base = ((size_t)s * WGRP + row) * KTOP;
            for (int q = 0; q < KTOP; q++) ins5(tv, ti, g_pv[base + q], g_pi[base + q]);
        }
        for (int q = 0; q < KTOP; q++) sidx[q] = ti[q];
    }
    __syncthreads();
    int t = threadIdx.x;
    float2 s = make_float2(0.f, 0.f);
#pragma unroll
    for (int q = 0; q < KTOP; q++) {
        float2 v = *(const float2*)(tb + (size_t)sidx[q] * D + t * 2);
        s.x += v.x; s.y += v.y;
    }
    s.x *= 0.2f; s.y *= 0.2f;
    *(float2*)(g_topk + (size_t)row * D + t * 2) = s;
}

// ---------------- Kernel E: out = topk_avg @ W^T + b ----------------
__global__ __launch_bounds__(256)
void k_out(const float* __restrict__ W, const float* __restrict__ bias, float* __restrict__ out) {
    __shared__ float As[16][68];
    __shared__ float Ws[16][68];
    int tid = threadIdx.x;
    int tx = tid & 15, ty = tid >> 4;
    int r0 = blockIdx.x * 64, o0 = blockIdx.y * 64;
    int lr = tid >> 2, k4 = tid & 3;
    const float* Ap = g_topk + (size_t)(r0 + lr) * D + k4 * 4;
    const float* Wp = W + (size_t)(o0 + lr) * D + k4 * 4;
    float acc[4][4] = {};
    float4 ra = *(const float4*)Ap;
    float4 rw = *(const float4*)Wp;
    for (int kb = 0; kb < 32; kb++) {
        As[k4 * 4 + 0][lr] = ra.x; As[k4 * 4 + 1][lr] = ra.y;
        As[k4 * 4 + 2][lr] = ra.z; As[k4 * 4 + 3][lr] = ra.w;
        Ws[k4 * 4 + 0][lr] = rw.x; Ws[k4 * 4 + 1][lr] = rw.y;
        Ws[k4 * 4 + 2][lr] = rw.z; Ws[k4 * 4 + 3][lr] = rw.w;
        __syncthreads();
        if (kb + 1 < 32) {
            ra = *(const float4*)(Ap + (kb + 1) * 16);
            rw = *(const float4*)(Wp + (kb + 1) * 16);
        }
#pragma unroll
        for (int k = 0; k < 16; k++) {
            float4 a = *(const float4*)&As[k][ty * 4];
            float4 w = *(const float4*)&Ws[k][tx * 4];
            float av[4] = {a.x, a.y, a.z, a.w}, wv[4] = {w.x, w.y, w.z, w.w};
#pragma unroll
            for (int i = 0; i < 4; i++)
#pragma unroll
                for (int j = 0; j < 4; j++) acc[i][j] += av[i] * wv[j];
        }
        __syncthreads();
    }
#pragma unroll
    for (int j = 0; j < 4; j++) {
        float bj = bias[o0 + tx * 4 + j];
#pragma unroll
        for (int i = 0; i < 4; i++)
            out[(size_t)(r0 + ty * 4 + i) * D + o0 + tx * 4 + j] = acc[i][j] + bj;
    }
}

extern "C" void kernel_launch(void* const* d_in, const int* in_sizes, int n_in,
                              void* d_out, int out_size) {
    const float* x  = (const float*)d_in[0];
    const float* tb = (const float*)d_in[1];
    const float* W  = (const float*)d_in[2];
    const float* b  = (const float*)d_in[3];
    float* out = (float*)d_out;

    k_avg_norm<<<WGRP, 128>>>(x);
    k_tinv<<<TB / 8, 256>>>(tb);
    k_cos_topk<<<dim3(WGRP / BM, SEGS), 256>>>(tb);
    k_merge_avg<<<WGRP, 256>>>(tb);
    k_out<<<dim3(WGRP / 64, D / 64), 256>>>(W, b, out);
}

// round 3
// speedup vs baseline: 1.5186x; 1.5186x over previous
#include <cuda_runtime.h>
#include <cuda_bf16.h>
#include <cstdint>

#define D      512
#define WGRP   1536
#define MGRP   64
#define TB     30000
#define TBP    30080
#define KTOP   5
#define NRT    12
#define NCT    235
#define BK     64
#define NCH    8
#define PLANE_B 16384                 // 128 rows x 128 B
#define STAGE_B (6 * PLANE_B)         // 96 KB
#define DSMEM_TOTAL (2 * STAGE_B)     // 192 KB
#define EPIT   132                    // epilogue row pitch (floats)

// ---------------- scratch ----------------
__device__ __nv_bfloat16 g_Asp[3][WGRP * D];
__device__ __nv_bfloat16 g_Bsp[3][TBP * D];
__device__ float g_invt[TBP];
__device__ float g_pv[(size_t)NCT * WGRP * KTOP];
__device__ int   g_pi[(size_t)NCT * WGRP * KTOP];
__device__ float g_topk[WGRP * D];

// ---------------- PTX helpers (sm_80-era only; no tcgen05) ----------------
__device__ __forceinline__ uint32_t smem_u32(const void* p) {
    uint32_t a;
    asm("{ .reg .u64 t; cvta.to.shared.u64 t, %1; cvt.u32.u64 %0, t; }" : "=r"(a) : "l"(p));
    return a;
}
__device__ __forceinline__ void cp16(uint32_t dst, const void* src) {
    asm volatile("cp.async.cg.shared.global [%0], [%1], 16;" :: "r"(dst), "l"(src));
}
__device__ __forceinline__ void cp_commit() {
    asm volatile("cp.async.commit_group;" ::: "memory");
}
template <int N>
__device__ __forceinline__ void cp_wait() {
    asm volatile("cp.async.wait_group %0;" :: "n"(N) : "memory");
}
__device__ __forceinline__ void ldsm_x4(uint32_t (&r)[4], uint32_t addr) {
    asm volatile("ldmatrix.sync.aligned.m8n8.x4.shared.b16 {%0,%1,%2,%3}, [%4];"
                 : "=r"(r[0]), "=r"(r[1]), "=r"(r[2]), "=r"(r[3]) : "r"(addr));
}
__device__ __forceinline__ void ldsm_x2(uint32_t (&r)[2], uint32_t addr) {
    asm volatile("ldmatrix.sync.aligned.m8n8.x2.shared.b16 {%0,%1}, [%2];"
                 : "=r"(r[0]), "=r"(r[1]) : "r"(addr));
}
__device__ __forceinline__ void mma16816(float (&d)[4], const uint32_t (&a)[4], const uint32_t (&b)[2]) {
    asm volatile(
        "mma.sync.aligned.m16n8k16.row.col.f32.bf16.bf16.f32 "
        "{%0,%1,%2,%3}, {%4,%5,%6,%7}, {%8,%9}, {%0,%1,%2,%3};"
        : "+f"(d[0]), "+f"(d[1]), "+f"(d[2]), "+f"(d[3])
        : "r"(a[0]), "r"(a[1]), "r"(a[2]), "r"(a[3]), "r"(b[0]), "r"(b[1]));
}

// ---------------- small helpers ----------------
__device__ __forceinline__ void ins5(float (&tv)[5], int (&ti)[5], float v, int c) {
    if (v > tv[4]) {
#pragma unroll
        for (int s = 0; s < 5; s++) {
            bool g = v > tv[s];
            float fn = g ? v : tv[s];
            float fo = g ? tv[s] : v;
            int   in_ = g ? c : ti[s];
            int   io  = g ? ti[s] : c;
            tv[s] = fn; v = fo; ti[s] = in_; c = io;
        }
    }
}
__device__ __forceinline__ void split3(float v, __nv_bfloat16& b0, __nv_bfloat16& b1, __nv_bfloat16& b2) {
    b0 = __float2bfloat16_rn(v);
    float r = v - __bfloat162float(b0);
    b1 = __float2bfloat16_rn(r);
    r -= __bfloat162float(b1);
    b2 = __float2bfloat16_rn(r);
}

// ---------------- Kernel A: group mean + normalize + bf16 3-way split ----------------
__global__ __launch_bounds__(128)
void k_avg_split(const float* __restrict__ x) {
    int g = blockIdx.x, t = threadIdx.x;
    const float* p = x + (size_t)g * (MGRP * D) + t * 4;
    float4 s0 = make_float4(0.f, 0.f, 0.f, 0.f), s1 = s0;
#pragma unroll 4
    for (int r = 0; r < MGRP; r += 2) {
        float4 a  = *(const float4*)(p + (size_t)r * D);
        float4 b2 = *(const float4*)(p + (size_t)(r + 1) * D);
        s0.x += a.x;  s0.y += a.y;  s0.z += a.z;  s0.w += a.w;
        s1.x += b2.x; s1.y += b2.y; s1.z += b2.z; s1.w += b2.w;
    }
    float4 m;
    m.x = (s0.x + s1.x) * (1.0f / 64.0f);
    m.y = (s0.y + s1.y) * (1.0f / 64.0f);
    m.z = (s0.z + s1.z) * (1.0f / 64.0f);
    m.w = (s0.w + s1.w) * (1.0f / 64.0f);
    float ss = m.x * m.x + m.y * m.y + m.z * m.z + m.w * m.w;
    __shared__ float red[128];
    red[t] = ss;
    __syncthreads();
    for (int o = 64; o > 0; o >>= 1) {
        if (t < o) red[t] += red[t + o];
        __syncthreads();
    }
    float inv = 1.0f / fmaxf(sqrtf(red[0]), 1e-8f);
    float v[4] = {m.x * inv, m.y * inv, m.z * inv, m.w * inv};
    size_t base = (size_t)g * D + t * 4;
    __nv_bfloat16 h0[4], h1[4], h2[4];
#pragma unroll
    for (int i = 0; i < 4; i++) split3(v[i], h0[i], h1[i], h2[i]);
#pragma unroll
    for (int i = 0; i < 4; i++) {
        g_Asp[0][base + i] = h0[i];
        g_Asp[1][base + i] = h1[i];
        g_Asp[2][base + i] = h2[i];
    }
}

// ---------------- Kernel B: text-bank inv-norm + bf16 3-way split (padded) ----------------
__global__ __launch_bounds__(128)
void k_bsplit(const float* __restrict__ tb) {
    int row = blockIdx.x, t = threadIdx.x;
    size_t base = (size_t)row * D + t * 4;
    if (row < TB) {
        float4 v4 = *(const float4*)(tb + base);
        float v[4] = {v4.x, v4.y, v4.z, v4.w};
        float ss = v[0] * v[0] + v[1] * v[1] + v[2] * v[2] + v[3] * v[3];
#pragma unroll
        for (int o = 16; o > 0; o >>= 1) ss += __shfl_xor_sync(0xffffffffu, ss, o);
        __shared__ float wsum[4];
        if ((t & 31) == 0) wsum[t >> 5] = ss;
        __syncthreads();
        float tot = wsum[0] + wsum[1] + wsum[2] + wsum[3];
        if (t == 0) g_invt[row] = 1.0f / fmaxf(sqrtf(tot), 1e-8f);
        __nv_bfloat16 h0[4], h1[4], h2[4];
#pragma unroll
        for (int i = 0; i < 4; i++) split3(v[i], h0[i], h1[i], h2[i]);
#pragma unroll
        for (int i = 0; i < 4; i++) {
            g_Bsp[0][base + i] = h0[i];
            g_Bsp[1][base + i] = h1[i];
            g_Bsp[2][base + i] = h2[i];
        }
    } else {
        __nv_bfloat16 z = __float2bfloat16_rn(0.0f);
        if (t == 0) g_invt[row] = 0.0f;
#pragma unroll
        for (int i = 0; i < 4; i++) {
            g_Bsp[0][base + i] = z;
            g_Bsp[1][base + i] = z;
            g_Bsp[2][base + i] = z;
        }
    }
}

// ---------------- Kernel C: mma.sync bf16 6-phase GEMM + fused top-5 ----------------
__global__ __launch_bounds__(256, 1)
void k_cos_topk() {
    extern __shared__ char dsm[];
    __shared__ float sInv[128];

    const int tid = threadIdx.x;
    const int wid = tid >> 5, lane = tid & 31;
    const int wr = wid >> 2, wc = wid & 3;         // 2 x 4 warp grid
    const int rowblk = blockIdx.x, coltile = blockIdx.y;

    if (tid < 128) sInv[tid] = g_invt[coltile * 128 + tid];

    const uint32_t sbase = smem_u32(dsm);

    // cp.async geometry: thread t handles rows r0 + 32*i (i=0..3), 16B chunk c of each plane
    const int r0 = tid >> 3;
    const int cch = tid & 7;
    const __nv_bfloat16* gA[3];
    const __nv_bfloat16* gB[3];
#pragma unroll
    for (int p = 0; p < 3; p++) {
        gA[p] = g_Asp[p] + (size_t)(rowblk * 128 + r0) * D + cch * 8;
        gB[p] = g_Bsp[p] + (size_t)(coltile * 128 + r0) * D + cch * 8;
    }

    // stage loader
    auto load_chunk = [&](int c, int buf) {
        uint32_t st = sbase + buf * STAGE_B;
#pragma unroll
        for (int p = 0; p < 3; p++) {
            const __nv_bfloat16* a = gA[p] + c * BK;
            const __nv_bfloat16* b = gB[p] + c * BK;
            uint32_t da = st + p * PLANE_B;
            uint32_t db = st + (3 + p) * PLANE_B;
#pragma unroll
            for (int i = 0; i < 4; i++) {
                int row = r0 + 32 * i;
                uint32_t soff = (uint32_t)row * 128 + ((uint32_t)(cch ^ (row & 7))) * 16;
                cp16(da + soff, a + (size_t)(32 * i) * D);
                cp16(db + soff, b + (size_t)(32 * i) * D);
            }
        }
        cp_commit();
    };

    load_chunk(0, 0);
    load_chunk(1, 1);

    float acc[4][4][4];
#pragma unroll
    for (int mt = 0; mt < 4; mt++)
#pragma unroll
        for (int nt = 0; nt < 4; nt++)
#pragma unroll
            for (int q = 0; q < 4; q++) acc[mt][nt][q] = 0.0f;

    // ldmatrix lane geometry (constant across chunks)
    const int a_m   = wr * 64 + (lane & 15);       // + mt*16
    const int a_kh  = lane >> 4;                   // k half (0/1)
    const int b_n   = wc * 32 + (lane & 7);        // + nt*8
    const int b_kh  = (lane >> 3) & 1;

    for (int c = 0; c < NCH; c++) {
        if (c == NCH - 1) cp_wait<0>(); else cp_wait<1>();
        __syncthreads();
        const uint32_t st = sbase + (c & 1) * STAGE_B;

#pragma unroll
        for (int ks = 0; ks < 4; ks++) {
#pragma unroll
            for (int pa = 0; pa < 3; pa++) {
                // A fragments, plane pa, k-step ks
                uint32_t afr[4][4];
#pragma unroll
                for (int mt = 0; mt < 4; mt++) {
                    int m = a_m + mt * 16;
                    uint32_t chunk = (uint32_t)(ks * 2 + a_kh);
                    uint32_t addr = st + pa * PLANE_B + (uint32_t)m * 128 + (chunk ^ (m & 7)) * 16;
                    ldsm_x4(afr[mt], addr);
                }
                const int npb = (pa == 0) ? 3 : (pa == 1 ? 2 : 1);
#pragma unroll
                for (int pb = 0; pb < 3; pb++) {
                    if (pb >= npb) break;
#pragma unroll
                    for (int nt = 0; nt < 4; nt++) {
                        int n = b_n + nt * 8;
                        uint32_t chunk = (uint32_t)(ks * 2 + b_kh);
                        uint32_t addr = st + (3 + pb) * PLANE_B + (uint32_t)n * 128 + (chunk ^ (n & 7)) * 16;
                        uint32_t bfr[2];
                        ldsm_x2(bfr, addr);
#pragma unroll
                        for (int mt = 0; mt < 4; mt++) mma16816(acc[mt][nt], afr[mt], bfr);
                    }
                }
            }
        }
        __syncthreads();
        if (c + 2 < NCH) load_chunk(c + 2, c & 1);
    }

    // ---- epilogue: spill cos tile to smem, scan top-5 per row ----
    float* eb = (float*)dsm;
    {
        const int rb = wr * 64 + (lane >> 2);
        const int cb = wc * 32 + (lane & 3) * 2;
#pragma unroll
        for (int mt = 0; mt < 4; mt++) {
#pragma unroll
            for (int nt = 0; nt < 4; nt++) {
                int r = rb + mt * 16, cc = cb + nt * 8;
                *(float2*)&eb[(size_t)r * EPIT + cc]       = make_float2(acc[mt][nt][0], acc[mt][nt][1]);
                *(float2*)&eb[(size_t)(r + 8) * EPIT + cc] = make_float2(acc[mt][nt][2], acc[mt][nt][3]);
            }
        }
    }
    __syncthreads();

    {
        const int row = tid >> 1, half = tid & 1;
        const int c0 = half * 64;
        float tv[5] = {-1e30f, -1e30f, -1e30f, -1e30f, -1e30f};
        int   ti[5] = {0, 0, 0, 0, 0};
        const float* er = eb + (size_t)row * EPIT;
#pragma unroll 8
        for (int j = 0; j < 64; j++) {
            int cl = c0 + j;
            int gc = coltile * 128 + cl;
            float v = er[cl] * sInv[cl];
            if (gc < TB) ins5(tv, ti, v, gc);
        }
        // merge the two halves (half 1 has strictly higher column indices)
        float ov[5]; int oi[5];
#pragma unroll
        for (int s = 0; s < 5; s++) {
            ov[s] = __shfl_xor_sync(0xffffffffu, tv[s], 1);
            oi[s] = __shfl_xor_sync(0xffffffffu, ti[s], 1);
        }
        if (half == 0) {
#pragma unroll
            for (int s = 0; s < 5; s++) ins5(tv, ti, ov[s], oi[s]);
            size_t pb = ((size_t)coltile * WGRP + rowblk * 128 + row) * KTOP;
#pragma unroll
            for (int s = 0; s < 5; s++) { g_pv[pb + s] = tv[s]; g_pi[pb + s] = ti[s]; }
        }
    }
}

// ---------------- Kernel D: warp-parallel merge of 235 tile partials + gather/mean ----------------
__global__ __launch_bounds__(256)
void k_merge_avg(const float* __restrict__ tb) {
    int row = blockIdx.x, t = threadIdx.x;
    __shared__ int sidx[KTOP];
    if (t < 32) {
        float tv[5] = {-1e30f, -1e30f, -1e30f, -1e30f, -1e30f};
        int   ti[5] = {0, 0, 0, 0, 0};
        int t0 = t * 8;
        for (int k = 0; k < 8; k++) {
            int tile = t0 + k;
            if (tile < NCT) {
                size_t b = ((size_t)tile * WGRP + row) * KTOP;
#pragma unroll
                for (int q = 0; q < KTOP; q++) ins5(tv, ti, g_pv[b + q], g_pi[b + q]);
            }
        }
#pragma unroll
        for (int r = 1; r <= 16; r <<= 1) {
            float ov[5]; int oi[5];
#pragma unroll
            for (int q = 0; q < 5; q++) {
                ov[q] = __shfl_xor_sync(0xffffffffu, tv[q], r);
                oi[q] = __shfl_xor_sync(0xffffffffu, ti[q], r);
            }
#pragma unroll
            for (int q = 0; q < 5; q++) ins5(tv, ti, ov[q], oi[q]);
        }
        if (t == 0) {
#pragma unroll
            for (int q = 0; q < KTOP; q++) sidx[q] = ti[q];
        }
    }
    __syncthreads();
    float2 s = make_float2(0.f, 0.f);
#pragma unroll
    for (int q = 0; q < KTOP; q++) {
        float2 v = *(const float2*)(tb + (size_t)sidx[q] * D + t * 2);
        s.x += v.x; s.y += v.y;
    }
    s.x *= 0.2f; s.y *= 0.2f;
    *(float2*)(g_topk + (size_t)row * D + t * 2) = s;
}

// ---------------- Kernel E: out = topk_avg @ W^T + b ----------------
__global__ __launch_bounds__(256)
void k_out(const float* __restrict__ W, const float* __restrict__ bias, float* __restrict__ out) {
    __shared__ float As[16][68];
    __shared__ float Ws[16][68];
    int tid = threadIdx.x;
    int tx = tid & 15, ty = tid >> 4;
    int r0 = blockIdx.x * 64, o0 = blockIdx.y * 64;
    int lr = tid >> 2, k4 = tid & 3;
    const float* Ap = g_topk + (size_t)(r0 + lr) * D + k4 * 4;
    const float* Wp = W + (size_t)(o0 + lr) * D + k4 * 4;
    float acc[4][4] = {};
    float4 ra = *(const float4*)Ap;
    float4 rw = *(const float4*)Wp;
    for (int kb = 0; kb < 32; kb++) {
        As[k4 * 4 + 0][lr] = ra.x; As[k4 * 4 + 1][lr] = ra.y;
        As[k4 * 4 + 2][lr] = ra.z; As[k4 * 4 + 3][lr] = ra.w;
        Ws[k4 * 4 + 0][lr] = rw.x; Ws[k4 * 4 + 1][lr] = rw.y;
        Ws[k4 * 4 + 2][lr] = rw.z; Ws[k4 * 4 + 3][lr] = rw.w;
        __syncthreads();
        if (kb + 1 < 32) {
            ra = *(const float4*)(Ap + (kb + 1) * 16);
            rw = *(const float4*)(Wp + (kb + 1) * 16);
        }
#pragma unroll
        for (int k = 0; k < 16; k++) {
            float4 a = *(const float4*)&As[k][ty * 4];
            float4 w = *(const float4*)&Ws[k][tx * 4];
            float av[4] = {a.x, a.y, a.z, a.w}, wv[4] = {w.x, w.y, w.z, w.w};
#pragma unroll
            for (int i = 0; i < 4; i++)
#pragma unroll
                for (int jj = 0; jj < 4; jj++) acc[i][jj] += av[i] * wv[jj];
        }
        __syncthreads();
    }
#pragma unroll
    for (int jj = 0; jj < 4; jj++) {
        float bj = bias[o0 + tx * 4 + jj];
#pragma unroll
        for (int i = 0; i < 4; i++)
            out[(size_t)(r0 + ty * 4 + i) * D + o0 + tx * 4 + jj] = acc[i][jj] + bj;
    }
}

extern "C" void kernel_launch(void* const* d_in, const int* in_sizes, int n_in,
                              void* d_out, int out_size) {
    const float* x  = (const float*)d_in[0];
    const float* tb = (const float*)d_in[1];
    const float* W  = (const float*)d_in[2];
    const float* b  = (const float*)d_in[3];
    float* out = (float*)d_out;

    cudaFuncSetAttribute(k_cos_topk, cudaFuncAttributeMaxDynamicSharedMemorySize, DSMEM_TOTAL);

    k_avg_split<<<WGRP, 128>>>(x);
    k_bsplit<<<TBP, 128>>>(tb);
    k_cos_topk<<<dim3(NRT, NCT), 256, DSMEM_TOTAL>>>();
    k_merge_avg<<<WGRP, 256>>>(tb);
    k_out<<<dim3(WGRP / 64, D / 64), 256>>>(W, b, out);
}

// round 4
// speedup vs baseline: 1.5544x; 1.0236x over previous
#include <cuda_runtime.h>
#include <cuda_fp16.h>
#include <cstdint>

#define D      512
#define WGRP   1536
#define MGRP   64
#define TB     30000
#define TBP    30080
#define KTOP   5
#define NRT    12
#define NCT    235
#define BK     64
#define NCH    8
#define PLANE_B 16384                 // 128 rows x 128 B
#define STAGE_B (4 * PLANE_B)         // 64 KB (A0,A1,B0,B1)
#define NSTAGE 3
#define DSMEM_TOTAL (NSTAGE * STAGE_B)  // 192 KB
#define EPIT   132
#define RSCALE 2048.0f
#define RINV   (1.0f / 2048.0f)

// ---------------- scratch ----------------
__device__ __half g_Asp[2][WGRP * D];
__device__ __half g_Bsp[2][TBP * D];
__device__ float g_invt[TBP];
__device__ float g_pv[(size_t)NCT * WGRP * KTOP];
__device__ int   g_pi[(size_t)NCT * WGRP * KTOP];
__device__ float g_topk[WGRP * D];

// ---------------- PTX helpers (sm_80-era only) ----------------
__device__ __forceinline__ uint32_t smem_u32(const void* p) {
    uint32_t a;
    asm("{ .reg .u64 t; cvta.to.shared.u64 t, %1; cvt.u32.u64 %0, t; }" : "=r"(a) : "l"(p));
    return a;
}
__device__ __forceinline__ void cp16(uint32_t dst, const void* src) {
    asm volatile("cp.async.cg.shared.global [%0], [%1], 16;" :: "r"(dst), "l"(src));
}
__device__ __forceinline__ void cp_commit() {
    asm volatile("cp.async.commit_group;" ::: "memory");
}
template <int N>
__device__ __forceinline__ void cp_wait() {
    asm volatile("cp.async.wait_group %0;" :: "n"(N) : "memory");
}
__device__ __forceinline__ void ldsm_x4(uint32_t (&r)[4], uint32_t addr) {
    asm volatile("ldmatrix.sync.aligned.m8n8.x4.shared.b16 {%0,%1,%2,%3}, [%4];"
                 : "=r"(r[0]), "=r"(r[1]), "=r"(r[2]), "=r"(r[3]) : "r"(addr));
}
__device__ __forceinline__ void mma16816(float (&d)[4], const uint32_t (&a)[4], const uint32_t* b) {
    asm volatile(
        "mma.sync.aligned.m16n8k16.row.col.f32.f16.f16.f32 "
        "{%0,%1,%2,%3}, {%4,%5,%6,%7}, {%8,%9}, {%0,%1,%2,%3};"
        : "+f"(d[0]), "+f"(d[1]), "+f"(d[2]), "+f"(d[3])
        : "r"(a[0]), "r"(a[1]), "r"(a[2]), "r"(a[3]), "r"(b[0]), "r"(b[1]));
}

// ---------------- tie-safe top-5 insert: order-independent lex (value desc, index asc) ----------------
__device__ __forceinline__ void ins5(float (&tv)[5], int (&ti)[5], float v, int c) {
    if ((v > tv[4]) || (v == tv[4] && c < ti[4])) {
#pragma unroll
        for (int s = 0; s < 5; s++) {
            bool g = (v > tv[s]) || (v == tv[s] && c < ti[s]);
            float fn = g ? v : tv[s];
            float fo = g ? tv[s] : v;
            int   in_ = g ? c : ti[s];
            int   io  = g ? ti[s] : c;
            tv[s] = fn; v = fo; ti[s] = in_; c = io;
        }
    }
}
__device__ __forceinline__ void split2(float v, __half& h0, __half& h1) {
    h0 = __float2half_rn(v);
    float r = v - __half2float(h0);
    h1 = __float2half_rn(r * RSCALE);
}

// ---------------- Kernel A: group mean + normalize + fp16 2-way split ----------------
__global__ __launch_bounds__(128)
void k_avg_split(const float* __restrict__ x) {
    int g = blockIdx.x, t = threadIdx.x;
    const float* p = x + (size_t)g * (MGRP * D) + t * 4;
    float4 s0 = make_float4(0.f, 0.f, 0.f, 0.f), s1 = s0;
#pragma unroll 4
    for (int r = 0; r < MGRP; r += 2) {
        float4 a  = *(const float4*)(p + (size_t)r * D);
        float4 b2 = *(const float4*)(p + (size_t)(r + 1) * D);
        s0.x += a.x;  s0.y += a.y;  s0.z += a.z;  s0.w += a.w;
        s1.x += b2.x; s1.y += b2.y; s1.z += b2.z; s1.w += b2.w;
    }
    float4 m;
    m.x = (s0.x + s1.x) * (1.0f / 64.0f);
    m.y = (s0.y + s1.y) * (1.0f / 64.0f);
    m.z = (s0.z + s1.z) * (1.0f / 64.0f);
    m.w = (s0.w + s1.w) * (1.0f / 64.0f);
    float ss = m.x * m.x + m.y * m.y + m.z * m.z + m.w * m.w;
    __shared__ float red[128];
    red[t] = ss;
    __syncthreads();
    for (int o = 64; o > 0; o >>= 1) {
        if (t < o) red[t] += red[t + o];
        __syncthreads();
    }
    float inv = 1.0f / fmaxf(sqrtf(red[0]), 1e-8f);
    float v[4] = {m.x * inv, m.y * inv, m.z * inv, m.w * inv};
    size_t base = (size_t)g * D + t * 4;
#pragma unroll
    for (int i = 0; i < 4; i++) {
        __half h0, h1; split2(v[i], h0, h1);
        g_Asp[0][base + i] = h0;
        g_Asp[1][base + i] = h1;
    }
}

// ---------------- Kernel B: text-bank inv-norm + fp16 2-way split (padded) ----------------
__global__ __launch_bounds__(128)
void k_bsplit(const float* __restrict__ tb) {
    int row = blockIdx.x, t = threadIdx.x;
    size_t base = (size_t)row * D + t * 4;
    if (row < TB) {
        float4 v4 = *(const float4*)(tb + base);
        float v[4] = {v4.x, v4.y, v4.z, v4.w};
        float ss = v[0] * v[0] + v[1] * v[1] + v[2] * v[2] + v[3] * v[3];
#pragma unroll
        for (int o = 16; o > 0; o >>= 1) ss += __shfl_xor_sync(0xffffffffu, ss, o);
        __shared__ float wsum[4];
        if ((t & 31) == 0) wsum[t >> 5] = ss;
        __syncthreads();
        float tot = wsum[0] + wsum[1] + wsum[2] + wsum[3];
        if (t == 0) g_invt[row] = 1.0f / fmaxf(sqrtf(tot), 1e-8f);
#pragma unroll
        for (int i = 0; i < 4; i++) {
            __half h0, h1; split2(v[i], h0, h1);
            g_Bsp[0][base + i] = h0;
            g_Bsp[1][base + i] = h1;
        }
    } else {
        __half z = __float2half_rn(0.0f);
        if (t == 0) g_invt[row] = 0.0f;
#pragma unroll
        for (int i = 0; i < 4; i++) {
            g_Bsp[0][base + i] = z;
            g_Bsp[1][base + i] = z;
        }
    }
}

// ---------------- Kernel C: fp16-split 3-phase HMMA GEMM + fused top-5 ----------------
__global__ __launch_bounds__(256, 1)
void k_cos_topk() {
    extern __shared__ char dsm[];
    __shared__ float sInv[128];

    const int tid = threadIdx.x;
    const int wid = tid >> 5, lane = tid & 31;
    const int wr = wid >> 2, wc = wid & 3;          // 2 x 4 warp grid, 64x32 warp tiles
    const int rowblk = blockIdx.x, coltile = blockIdx.y;

    if (tid < 128) sInv[tid] = g_invt[coltile * 128 + tid];

    const uint32_t sbase = smem_u32(dsm);

    // cp.async geometry: thread t handles rows r0 + 32*i (i<4), 16B chunk cch of each plane
    const int r0 = tid >> 3;
    const int cch = tid & 7;
    const __half* gA[2];
    const __half* gB[2];
#pragma unroll
    for (int p = 0; p < 2; p++) {
        gA[p] = g_Asp[p] + (size_t)(rowblk * 128 + r0) * D + cch * 8;
        gB[p] = g_Bsp[p] + (size_t)(coltile * 128 + r0) * D + cch * 8;
    }

    auto load_chunk = [&](int c, int buf) {
        uint32_t st = sbase + buf * STAGE_B;
#pragma unroll
        for (int p = 0; p < 2; p++) {
            const __half* a = gA[p] + c * BK;
            const __half* b = gB[p] + c * BK;
            uint32_t da = st + p * PLANE_B;
            uint32_t db = st + (2 + p) * PLANE_B;
#pragma unroll
            for (int i = 0; i < 4; i++) {
                int row = r0 + 32 * i;
                uint32_t soff = (uint32_t)row * 128 + ((uint32_t)(cch ^ (row & 7))) * 16;
                cp16(da + soff, a + (size_t)(32 * i) * D);
                cp16(db + soff, b + (size_t)(32 * i) * D);
            }
        }
        cp_commit();
    };

    load_chunk(0, 0);
    load_chunk(1, 1);
    load_chunk(2, 2);

    float accP[4][4][4], accQ[4][4][4];
#pragma unroll
    for (int mt = 0; mt < 4; mt++)
#pragma unroll
        for (int nt = 0; nt < 4; nt++)
#pragma unroll
            for (int q = 0; q < 4; q++) { accP[mt][nt][q] = 0.0f; accQ[mt][nt][q] = 0.0f; }

    // ldmatrix lane geometry
    const int a_m  = wr * 64 + (lane & 15);               // + mt*16
    const int a_kh = lane >> 4;                           // k half
    const int b_n  = wc * 32 + (lane & 7) + ((lane >> 4) & 1) * 8;  // + ntp*16
    const int b_kh = (lane >> 3) & 1;

    for (int c = 0; c < NCH; c++) {
        if (c <= NCH - 3) cp_wait<2>(); else if (c == NCH - 2) cp_wait<1>(); else cp_wait<0>();
        __syncthreads();
        const uint32_t st = sbase + (c % 3) * STAGE_B;

#pragma unroll
        for (int ks = 0; ks < 4; ks++) {
            uint32_t a0f[4][4], a1f[4][4];
#pragma unroll
            for (int mt = 0; mt < 4; mt++) {
                int m = a_m + mt * 16;
                uint32_t chunk = (uint32_t)(ks * 2 + a_kh);
                uint32_t off = (uint32_t)m * 128 + (chunk ^ (m & 7)) * 16;
                ldsm_x4(a0f[mt], st + off);
                ldsm_x4(a1f[mt], st + PLANE_B + off);
            }
            uint32_t b0f[8], b1f[8];   // 4 nt x 2 regs
#pragma unroll
            for (int ntp = 0; ntp < 2; ntp++) {
                int n = b_n + ntp * 16;
                uint32_t chunk = (uint32_t)(ks * 2 + b_kh);
                uint32_t off = (uint32_t)n * 128 + (chunk ^ (n & 7)) * 16;
                uint32_t r4[4];
                ldsm_x4(r4, st + 2 * PLANE_B + off);
                b0f[ntp * 4 + 0] = r4[0]; b0f[ntp * 4 + 1] = r4[1];
                b0f[ntp * 4 + 2] = r4[2]; b0f[ntp * 4 + 3] = r4[3];
                ldsm_x4(r4, st + 3 * PLANE_B + off);
                b1f[ntp * 4 + 0] = r4[0]; b1f[ntp * 4 + 1] = r4[1];
                b1f[ntp * 4 + 2] = r4[2]; b1f[ntp * 4 + 3] = r4[3];
            }
#pragma unroll
            for (int mt = 0; mt < 4; mt++) {
#pragma unroll
                for (int nt = 0; nt < 4; nt++) {
                    mma16816(accP[mt][nt], a0f[mt], &b0f[nt * 2]);
                    mma16816(accQ[mt][nt], a0f[mt], &b1f[nt * 2]);
                    mma16816(accQ[mt][nt], a1f[mt], &b0f[nt * 2]);
                }
            }
        }
        __syncthreads();
        if (c + 3 < NCH) load_chunk(c + 3, c % 3);
    }

    // ---- epilogue: combine P + Q/2048, spill to smem, scan top-5 per row ----
    float* eb = (float*)dsm;
    {
        const int rb = wr * 64 + (lane >> 2);
        const int cb = wc * 32 + (lane & 3) * 2;
#pragma unroll
        for (int mt = 0; mt < 4; mt++) {
#pragma unroll
            for (int nt = 0; nt < 4; nt++) {
                int r = rb + mt * 16, cc = cb + nt * 8;
                float v0 = accP[mt][nt][0] + accQ[mt][nt][0] * RINV;
                float v1 = accP[mt][nt][1] + accQ[mt][nt][1] * RINV;
                float v2 = accP[mt][nt][2] + accQ[mt][nt][2] * RINV;
                float v3 = accP[mt][nt][3] + accQ[mt][nt][3] * RINV;
                *(float2*)&eb[(size_t)r * EPIT + cc]       = make_float2(v0, v1);
                *(float2*)&eb[(size_t)(r + 8) * EPIT + cc] = make_float2(v2, v3);
            }
        }
    }
    __syncthreads();

    {
        const int row = tid >> 1, half = tid & 1;
        const int c0 = half * 64;
        float tv[5] = {-1e30f, -1e30f, -1e30f, -1e30f, -1e30f};
        int   ti[5] = {0, 0, 0, 0, 0};
        const float* er = eb + (size_t)row * EPIT;
#pragma unroll 8
        for (int j = 0; j < 64; j++) {
            int cl = c0 + j;
            int gc = coltile * 128 + cl;
            float v = er[cl] * sInv[cl];
            if (gc < TB) ins5(tv, ti, v, gc);
        }
        float ov[5]; int oi[5];
#pragma unroll
        for (int s = 0; s < 5; s++) {
            ov[s] = __shfl_xor_sync(0xffffffffu, tv[s], 1);
            oi[s] = __shfl_xor_sync(0xffffffffu, ti[s], 1);
        }
        if (half == 0) {
#pragma unroll
            for (int s = 0; s < 5; s++) ins5(tv, ti, ov[s], oi[s]);
            size_t pb = ((size_t)coltile * WGRP + rowblk * 128 + row) * KTOP;
#pragma unroll
            for (int s = 0; s < 5; s++) { g_pv[pb + s] = tv[s]; g_pi[pb + s] = ti[s]; }
        }
    }
}

// ---------------- Kernel D: parallel merge of 235 tile partials + gather/mean ----------------
__global__ __launch_bounds__(256)
void k_merge_avg(const float* __restrict__ tb) {
    int row = blockIdx.x, t = threadIdx.x;
    int lane = t & 31, w = t >> 5;
    __shared__ float sv[8][5];
    __shared__ int   si[8][5];
    __shared__ int   sidx[KTOP];

    float tv[5] = {-1e30f, -1e30f, -1e30f, -1e30f, -1e30f};
    int   ti[5] = {0, 0, 0, 0, 0};
    if (t < NCT) {
        size_t b = ((size_t)t * WGRP + row) * KTOP;
#pragma unroll
        for (int q = 0; q < KTOP; q++) ins5(tv, ti, g_pv[b + q], g_pi[b + q]);
    }
#pragma unroll
    for (int r = 1; r <= 16; r <<= 1) {
        float ov[5]; int oi[5];
#pragma unroll
        for (int q = 0; q < 5; q++) {
            ov[q] = __shfl_xor_sync(0xffffffffu, tv[q], r);
            oi[q] = __shfl_xor_sync(0xffffffffu, ti[q], r);
        }
#pragma unroll
        for (int q = 0; q < 5; q++) ins5(tv, ti, ov[q], oi[q]);
    }
    if (lane == 0) {
#pragma unroll
        for (int q = 0; q < 5; q++) { sv[w][q] = tv[q]; si[w][q] = ti[q]; }
    }
    __syncthreads();
    if (w == 0) {
        float mv[5]; int mi[5];
#pragma unroll
        for (int q = 0; q < 5; q++) {
            mv[q] = (lane < 8) ? sv[lane][q] : -1e30f;
            mi[q] = (lane < 8) ? si[lane][q] : 0;
        }
#pragma unroll
        for (int r = 1; r <= 4; r <<= 1) {
            float ov[5]; int oi[5];
#pragma unroll
            for (int q = 0; q < 5; q++) {
                ov[q] = __shfl_xor_sync(0xffffffffu, mv[q], r);
                oi[q] = __shfl_xor_sync(0xffffffffu, mi[q], r);
            }
#pragma unroll
            for (int q = 0; q < 5; q++) ins5(mv, mi, ov[q], oi[q]);
        }
        if (lane == 0) {
#pragma unroll
            for (int q = 0; q < KTOP; q++) sidx[q] = mi[q];
        }
    }
    __syncthreads();
    float2 s = make_float2(0.f, 0.f);
#pragma unroll
    for (int q = 0; q < KTOP; q++) {
        float2 v = *(const float2*)(tb + (size_t)sidx[q] * D + t * 2);
        s.x += v.x; s.y += v.y;
    }
    s.x *= 0.2f; s.y *= 0.2f;
    *(float2*)(g_topk + (size_t)row * D + t * 2) = s;
}

// ---------------- Kernel E: out = topk_avg @ W^T + b ----------------
__global__ __launch_bounds__(256)
void k_out(const float* __restrict__ W, const float* __restrict__ bias, float* __restrict__ out) {
    __shared__ float As[16][68];
    __shared__ float Ws[16][68];
    int tid = threadIdx.x;
    int tx = tid & 15, ty = tid >> 4;
    int r0 = blockIdx.x * 64, o0 = blockIdx.y * 64;
    int lr = tid >> 2, k4 = tid & 3;
    const float* Ap = g_topk + (size_t)(r0 + lr) * D + k4 * 4;
    const float* Wp = W + (size_t)(o0 + lr) * D + k4 * 4;
    float acc[4][4] = {};
    float4 ra = *(const float4*)Ap;
    float4 rw = *(const float4*)Wp;
    for (int kb = 0; kb < 32; kb++) {
        As[k4 * 4 + 0][lr] = ra.x; As[k4 * 4 + 1][lr] = ra.y;
        As[k4 * 4 + 2][lr] = ra.z; As[k4 * 4 + 3][lr] = ra.w;
        Ws[k4 * 4 + 0][lr] = rw.x; Ws[k4 * 4 + 1][lr] = rw.y;
        Ws[k4 * 4 + 2][lr] = rw.z; Ws[k4 * 4 + 3][lr] = rw.w;
        __syncthreads();
        if (kb + 1 < 32) {
            ra = *(const float4*)(Ap + (kb + 1) * 16);
            rw = *(const float4*)(Wp + (kb + 1) * 16);
        }
#pragma unroll
        for (int k = 0; k < 16; k++) {
            float4 a = *(const float4*)&As[k][ty * 4];
            float4 w = *(const float4*)&Ws[k][tx * 4];
            float av[4] = {a.x, a.y, a.z, a.w}, wv[4] = {w.x, w.y, w.z, w.w};
#pragma unroll
            for (int i = 0; i < 4; i++)
#pragma unroll
                for (int jj = 0; jj < 4; jj++) acc[i][jj] += av[i] * wv[jj];
        }
        __syncthreads();
    }
#pragma unroll
    for (int jj = 0; jj < 4; jj++) {
        float bj = bias[o0 + tx * 4 + jj];
#pragma unroll
        for (int i = 0; i < 4; i++)
            out[(size_t)(r0 + ty * 4 + i) * D + o0 + tx * 4 + jj] = acc[i][jj] + bj;
    }
}

extern "C" void kernel_launch(void* const* d_in, const int* in_sizes, int n_in,
                              void* d_out, int out_size) {
    const float* x  = (const float*)d_in[0];
    const float* tb = (const float*)d_in[1];
    const float* W  = (const float*)d_in[2];
    const float* b  = (const float*)d_in[3];
    float* out = (float*)d_out;

    cudaFuncSetAttribute(k_cos_topk, cudaFuncAttributeMaxDynamicSharedMemorySize, DSMEM_TOTAL);

    k_avg_split<<<WGRP, 128>>>(x);
    k_bsplit<<<TBP, 128>>>(tb);
    k_cos_topk<<<dim3(NRT, NCT), 256, DSMEM_TOTAL>>>();
    k_merge_avg<<<WGRP, 256>>>(tb);
    k_out<<<dim3(WGRP / 64, D / 64), 256>>>(W, b, out);
}

// round 5
// speedup vs baseline: 3.7023x; 2.3818x over previous
#include <cuda_runtime.h>
#include <cuda_fp16.h>
#include <cstdint>

#define D      512
#define WGRP   1536
#define MGRP   64
#define TB     30000
#define TBP    30080
#define KTOP   5
#define NRT    12
#define NCT    235
#define BK     64
#define NCH    8
#define PLANE_B 16384                 // 128 rows x 128 B (fp16)
#define STAGE_B (2 * PLANE_B)         // 32 KB (A, B)
#define NSTAGE 3
#define DSMEM_TOTAL (NSTAGE * STAGE_B)  // 96 KB
#define MARGIN 6e-3f
#define MAXCAND 128

// ---------------- scratch ----------------
__device__ __half g_Ah[WGRP * D];
__device__ __half g_Bh[TBP * D];
__device__ float  g_a[WGRP * D];
__device__ float  g_invt[TBP];
__device__ __half g_cos[(size_t)WGRP * TBP];
__device__ float  g_topk[WGRP * D];

// ---------------- PTX helpers (sm_80-era only) ----------------
__device__ __forceinline__ uint32_t smem_u32(const void* p) {
    uint32_t a;
    asm("{ .reg .u64 t; cvta.to.shared.u64 t, %1; cvt.u32.u64 %0, t; }" : "=r"(a) : "l"(p));
    return a;
}
__device__ __forceinline__ void cp16(uint32_t dst, const void* src) {
    asm volatile("cp.async.cg.shared.global [%0], [%1], 16;" :: "r"(dst), "l"(src));
}
__device__ __forceinline__ void cp_commit() {
    asm volatile("cp.async.commit_group;" ::: "memory");
}
template <int N>
__device__ __forceinline__ void cp_wait() {
    asm volatile("cp.async.wait_group %0;" :: "n"(N) : "memory");
}
__device__ __forceinline__ void ldsm_x4(uint32_t (&r)[4], uint32_t addr) {
    asm volatile("ldmatrix.sync.aligned.m8n8.x4.shared.b16 {%0,%1,%2,%3}, [%4];"
                 : "=r"(r[0]), "=r"(r[1]), "=r"(r[2]), "=r"(r[3]) : "r"(addr));
}
__device__ __forceinline__ void mma16816(float (&d)[4], const uint32_t (&a)[4], const uint32_t* b) {
    asm volatile(
        "mma.sync.aligned.m16n8k16.row.col.f32.f16.f16.f32 "
        "{%0,%1,%2,%3}, {%4,%5,%6,%7}, {%8,%9}, {%0,%1,%2,%3};"
        : "+f"(d[0]), "+f"(d[1]), "+f"(d[2]), "+f"(d[3])
        : "r"(a[0]), "r"(a[1]), "r"(a[2]), "r"(a[3]), "r"(b[0]), "r"(b[1]));
}

// ---------------- top-5 values-only insert ----------------
__device__ __forceinline__ void ins5v(float (&tv)[5], float v) {
    if (v > tv[4]) {
#pragma unroll
        for (int s = 0; s < 5; s++) {
            float hi = fmaxf(tv[s], v);
            float lo = fminf(tv[s], v);
            tv[s] = hi; v = lo;
        }
    }
}

// ---------------- Kernel A: group mean + normalize -> fp32 + fp16 ----------------
__global__ __launch_bounds__(128)
void k_avg_split(const float* __restrict__ x) {
    int g = blockIdx.x, t = threadIdx.x;
    const float* p = x + (size_t)g * (MGRP * D) + t * 4;
    float4 s0 = make_float4(0.f, 0.f, 0.f, 0.f), s1 = s0;
#pragma unroll 4
    for (int r = 0; r < MGRP; r += 2) {
        float4 a  = *(const float4*)(p + (size_t)r * D);
        float4 b2 = *(const float4*)(p + (size_t)(r + 1) * D);
        s0.x += a.x;  s0.y += a.y;  s0.z += a.z;  s0.w += a.w;
        s1.x += b2.x; s1.y += b2.y; s1.z += b2.z; s1.w += b2.w;
    }
    float4 m;
    m.x = (s0.x + s1.x) * (1.0f / 64.0f);
    m.y = (s0.y + s1.y) * (1.0f / 64.0f);
    m.z = (s0.z + s1.z) * (1.0f / 64.0f);
    m.w = (s0.w + s1.w) * (1.0f / 64.0f);
    float ss = m.x * m.x + m.y * m.y + m.z * m.z + m.w * m.w;
    __shared__ float red[128];
    red[t] = ss;
    __syncthreads();
    for (int o = 64; o > 0; o >>= 1) {
        if (t < o) red[t] += red[t + o];
        __syncthreads();
    }
    float inv = 1.0f / fmaxf(sqrtf(red[0]), 1e-8f);
    float v[4] = {m.x * inv, m.y * inv, m.z * inv, m.w * inv};
    size_t base = (size_t)g * D + t * 4;
    *(float4*)(g_a + base) = make_float4(v[0], v[1], v[2], v[3]);
#pragma unroll
    for (int i = 0; i < 4; i++) g_Ah[base + i] = __float2half_rn(v[i]);
}

// ---------------- Kernel B: text-bank inv-norm + fp16 cast (padded) ----------------
__global__ __launch_bounds__(128)
void k_bsplit(const float* __restrict__ tb) {
    int row = blockIdx.x, t = threadIdx.x;
    size_t base = (size_t)row * D + t * 4;
    if (row < TB) {
        float4 v4 = *(const float4*)(tb + base);
        float v[4] = {v4.x, v4.y, v4.z, v4.w};
        float ss = v[0] * v[0] + v[1] * v[1] + v[2] * v[2] + v[3] * v[3];
#pragma unroll
        for (int o = 16; o > 0; o >>= 1) ss += __shfl_xor_sync(0xffffffffu, ss, o);
        __shared__ float wsum[4];
        if ((t & 31) == 0) wsum[t >> 5] = ss;
        __syncthreads();
        float tot = wsum[0] + wsum[1] + wsum[2] + wsum[3];
        if (t == 0) g_invt[row] = 1.0f / fmaxf(sqrtf(tot), 1e-8f);
#pragma unroll
        for (int i = 0; i < 4; i++) g_Bh[base + i] = __float2half_rn(v[i]);
    } else {
        __half z = __float2half_rn(0.0f);
        if (t == 0) g_invt[row] = 0.0f;
#pragma unroll
        for (int i = 0; i < 4; i++) g_Bh[base + i] = z;
    }
}

// ---------------- Kernel C: single-phase fp16 HMMA GEMM -> scaled fp16 cos ----------------
__global__ __launch_bounds__(256, 2)
void k_gemm() {
    extern __shared__ char dsm[];
    __shared__ float sInv[128];

    const int tid = threadIdx.x;
    const int wid = tid >> 5, lane = tid & 31;
    const int wr = wid >> 2, wc = wid & 3;          // 2 x 4 warp grid, 64x32 warp tiles
    const int rowblk = blockIdx.x, coltile = blockIdx.y;

    if (tid < 128) sInv[tid] = g_invt[coltile * 128 + tid];

    const uint32_t sbase = smem_u32(dsm);

    const int r0 = tid >> 3;
    const int cch = tid & 7;
    const __half* gA = g_Ah + (size_t)(rowblk * 128 + r0) * D + cch * 8;
    const __half* gB = g_Bh + (size_t)(coltile * 128 + r0) * D + cch * 8;

    auto load_chunk = [&](int c, int buf) {
        uint32_t st = sbase + buf * STAGE_B;
        const __half* a = gA + c * BK;
        const __half* b = gB + c * BK;
#pragma unroll
        for (int i = 0; i < 4; i++) {
            int row = r0 + 32 * i;
            uint32_t soff = (uint32_t)row * 128 + ((uint32_t)(cch ^ (row & 7))) * 16;
            cp16(st + soff, a + (size_t)(32 * i) * D);
            cp16(st + PLANE_B + soff, b + (size_t)(32 * i) * D);
        }
        cp_commit();
    };

    load_chunk(0, 0);
    load_chunk(1, 1);
    load_chunk(2, 2);

    float acc[4][4][4];
#pragma unroll
    for (int mt = 0; mt < 4; mt++)
#pragma unroll
        for (int nt = 0; nt < 4; nt++)
#pragma unroll
            for (int q = 0; q < 4; q++) acc[mt][nt][q] = 0.0f;

    const int a_m  = wr * 64 + (lane & 15);
    const int a_kh = lane >> 4;
    const int b_n  = wc * 32 + (lane & 7) + ((lane >> 4) & 1) * 8;
    const int b_kh = (lane >> 3) & 1;

    for (int c = 0; c < NCH; c++) {
        if (c <= NCH - 3) cp_wait<2>(); else if (c == NCH - 2) cp_wait<1>(); else cp_wait<0>();
        __syncthreads();
        const uint32_t st = sbase + (c % 3) * STAGE_B;

#pragma unroll
        for (int ks = 0; ks < 4; ks++) {
            uint32_t af[4][4];
#pragma unroll
            for (int mt = 0; mt < 4; mt++) {
                int m = a_m + mt * 16;
                uint32_t chunk = (uint32_t)(ks * 2 + a_kh);
                ldsm_x4(af[mt], st + (uint32_t)m * 128 + (chunk ^ (m & 7)) * 16);
            }
            uint32_t bf[8];
#pragma unroll
            for (int ntp = 0; ntp < 2; ntp++) {
                int n = b_n + ntp * 16;
                uint32_t chunk = (uint32_t)(ks * 2 + b_kh);
                uint32_t r4[4];
                ldsm_x4(r4, st + PLANE_B + (uint32_t)n * 128 + (chunk ^ (n & 7)) * 16);
                bf[ntp * 4 + 0] = r4[0]; bf[ntp * 4 + 1] = r4[1];
                bf[ntp * 4 + 2] = r4[2]; bf[ntp * 4 + 3] = r4[3];
            }
#pragma unroll
            for (int mt = 0; mt < 4; mt++)
#pragma unroll
                for (int nt = 0; nt < 4; nt++)
                    mma16816(acc[mt][nt], af[mt], &bf[nt * 2]);
        }
        __syncthreads();
        if (c + 3 < NCH) load_chunk(c + 3, c % 3);
    }

    // ---- epilogue: scale + store fp16 directly from fragments ----
    const int rb = wr * 64 + (lane >> 2);
    const int cb = wc * 32 + (lane & 3) * 2;
    const size_t grow0 = (size_t)(rowblk * 128);
    const int gcol0 = coltile * 128;
#pragma unroll
    for (int mt = 0; mt < 4; mt++) {
#pragma unroll
        for (int nt = 0; nt < 4; nt++) {
            int r = rb + mt * 16, cc = cb + nt * 8;
            float i0 = sInv[cc], i1 = sInv[cc + 1];
            __half2 h0 = __floats2half2_rn(acc[mt][nt][0] * i0, acc[mt][nt][1] * i1);
            __half2 h1 = __floats2half2_rn(acc[mt][nt][2] * i0, acc[mt][nt][3] * i1);
            *(__half2*)&g_cos[(grow0 + r)     * TBP + gcol0 + cc] = h0;
            *(__half2*)&g_cos[(grow0 + r + 8) * TBP + gcol0 + cc] = h1;
        }
    }
}

// ---------------- Kernel D: scan -> threshold -> exact rescore -> top5 -> mean ----------------
__global__ __launch_bounds__(256)
void k_select(const float* __restrict__ tb) {
    const int row = blockIdx.x, t = threadIdx.x;
    const int lane = t & 31, w = t >> 5;
    const __half2* crow = (const __half2*)(g_cos + (size_t)row * TBP);

    __shared__ float s_top[8][5];
    __shared__ float s_thresh;
    __shared__ int   s_cnt;
    __shared__ int   s_cand[MAXCAND];
    __shared__ double s_cval[MAXCAND];
    __shared__ int   s_sel[KTOP];

    // ---- pass 1: 5th-largest stored value ----
    float tv[5] = {-1e30f, -1e30f, -1e30f, -1e30f, -1e30f};
    for (int i = t; i < TB / 2; i += 256) {   // cols < 30000 only (pad excluded)
        __half2 h = crow[i];
        ins5v(tv, __low2float(h));
        ins5v(tv, __high2float(h));
    }
#pragma unroll
    for (int r = 1; r <= 16; r <<= 1) {
        float ov[5];
#pragma unroll
        for (int q = 0; q < 5; q++) ov[q] = __shfl_xor_sync(0xffffffffu, tv[q], r);
#pragma unroll
        for (int q = 0; q < 5; q++) ins5v(tv, ov[q]);
    }
    if (lane == 0) {
#pragma unroll
        for (int q = 0; q < 5; q++) s_top[w][q] = tv[q];
    }
    if (t == 0) s_cnt = 0;
    __syncthreads();
    if (t == 0) {
        float mv[5] = {-1e30f, -1e30f, -1e30f, -1e30f, -1e30f};
        for (int ww = 0; ww < 8; ww++)
#pragma unroll
            for (int q = 0; q < 5; q++) ins5v(mv, s_top[ww][q]);
        s_thresh = mv[4] - MARGIN;
    }
    __syncthreads();
    const float thresh = s_thresh;

    // ---- pass 2: collect candidates ----
    for (int i = t; i < TB / 2; i += 256) {
        __half2 h = crow[i];
        float v0 = __low2float(h), v1 = __high2float(h);
        if (v0 >= thresh) {
            int slot = atomicAdd(&s_cnt, 1);
            if (slot < MAXCAND) s_cand[slot] = 2 * i;
        }
        if (v1 >= thresh) {
            int slot = atomicAdd(&s_cnt, 1);
            if (slot < MAXCAND) s_cand[slot] = 2 * i + 1;
        }
    }
    __syncthreads();
    const int ncand = min(s_cnt, MAXCAND);

    // ---- exact rescore (double accumulation): one warp per candidate ----
    const float* arow = g_a + (size_t)row * D;
    for (int ci = w; ci < ncand; ci += 8) {
        int c = s_cand[ci];
        const float* trow = tb + (size_t)c * D;
        double acc = 0.0;
#pragma unroll
        for (int j = 0; j < 16; j++) {
            int idx = lane + 32 * j;
            acc += (double)arow[idx] * (double)trow[idx];
        }
#pragma unroll
        for (int o = 16; o > 0; o >>= 1) acc += __shfl_xor_sync(0xffffffffu, acc, o);
        if (lane == 0) s_cval[ci] = acc * (double)g_invt[c];
    }
    __syncthreads();

    // ---- top-5 by (value desc, index asc) ----
    if (t == 0) {
        bool used[MAXCAND];
        for (int i = 0; i < ncand; i++) used[i] = false;
#pragma unroll
        for (int s = 0; s < KTOP; s++) {
            int best = -1;
            double bv = -1e300; int bi = 0x7fffffff;
            for (int i = 0; i < ncand; i++) {
                if (used[i]) continue;
                double v = s_cval[i]; int c = s_cand[i];
                if (v > bv || (v == bv && c < bi)) { bv = v; bi = c; best = i; }
            }
            used[best] = true;
            s_sel[s] = s_cand[best];
        }
    }
    __syncthreads();

    // ---- gather + mean ----
    float2 s = make_float2(0.f, 0.f);
#pragma unroll
    for (int q = 0; q < KTOP; q++) {
        float2 v = *(const float2*)(tb + (size_t)s_sel[q] * D + t * 2);
        s.x += v.x; s.y += v.y;
    }
    s.x *= 0.2f; s.y *= 0.2f;
    *(float2*)(g_topk + (size_t)row * D + t * 2) = s;
}

// ---------------- Kernel E: out = topk_avg @ W^T + b ----------------
__global__ __launch_bounds__(256)
void k_out(const float* __restrict__ W, const float* __restrict__ bias, float* __restrict__ out) {
    __shared__ float As[16][68];
    __shared__ float Ws[16][68];
    int tid = threadIdx.x;
    int tx = tid & 15, ty = tid >> 4;
    int r0 = blockIdx.x * 64, o0 = blockIdx.y * 64;
    int lr = tid >> 2, k4 = tid & 3;
    const float* Ap = g_topk + (size_t)(r0 + lr) * D + k4 * 4;
    const float* Wp = W + (size_t)(o0 + lr) * D + k4 * 4;
    float acc[4][4] = {};
    float4 ra = *(const float4*)Ap;
    float4 rw = *(const float4*)Wp;
    for (int kb = 0; kb < 32; kb++) {
        As[k4 * 4 + 0][lr] = ra.x; As[k4 * 4 + 1][lr] = ra.y;
        As[k4 * 4 + 2][lr] = ra.z; As[k4 * 4 + 3][lr] = ra.w;
        Ws[k4 * 4 + 0][lr] = rw.x; Ws[k4 * 4 + 1][lr] = rw.y;
        Ws[k4 * 4 + 2][lr] = rw.z; Ws[k4 * 4 + 3][lr] = rw.w;
        __syncthreads();
        if (kb + 1 < 32) {
            ra = *(const float4*)(Ap + (kb + 1) * 16);
            rw = *(const float4*)(Wp + (kb + 1) * 16);
        }
#pragma unroll
        for (int k = 0; k < 16; k++) {
            float4 a = *(const float4*)&As[k][ty * 4];
            float4 w = *(const float4*)&Ws[k][tx * 4];
            float av[4] = {a.x, a.y, a.z, a.w}, wv[4] = {w.x, w.y, w.z, w.w};
#pragma unroll
            for (int i = 0; i < 4; i++)
#pragma unroll
                for (int jj = 0; jj < 4; jj++) acc[i][jj] += av[i] * wv[jj];
        }
        __syncthreads();
    }
#pragma unroll
    for (int jj = 0; jj < 4; jj++) {
        float bj = bias[o0 + tx * 4 + jj];
#pragma unroll
        for (int i = 0; i < 4; i++)
            out[(size_t)(r0 + ty * 4 + i) * D + o0 + tx * 4 + jj] = acc[i][jj] + bj;
    }
}

extern "C" void kernel_launch(void* const* d_in, const int* in_sizes, int n_in,
                              void* d_out, int out_size) {
    const float* x  = (const float*)d_in[0];
    const float* tb = (const float*)d_in[1];
    const float* W  = (const float*)d_in[2];
    const float* b  = (const float*)d_in[3];
    float* out = (float*)d_out;

    cudaFuncSetAttribute(k_gemm, cudaFuncAttributeMaxDynamicSharedMemorySize, DSMEM_TOTAL);

    k_avg_split<<<WGRP, 128>>>(x);
    k_bsplit<<<TBP, 128>>>(tb);
    k_gemm<<<dim3(NRT, NCT), 256, DSMEM_TOTAL>>>();
    k_select<<<WGRP, 256>>>(tb);
    k_out<<<dim3(WGRP / 64, D / 64), 256>>>(W, b, out);
}